// round 16
// baseline (speedup 1.0000x reference)
#include <cuda_runtime.h>
#include <math.h>

// ---------------------------------------------------------------------------
// RoutingStorage (GR4J). Single fused kernel: per-block staging (raw x ->
// pr -> FIR c1/c2 in smem), per-block warm-start solve (local mean ->
// 12 fixed-point iters), chunk-parallel warmup scan.
// R16: iterCost law {K=1:157, K=2:150, K=4:295} explained: K=2's 1-instr
// interleave covers only 2/4 cyc latency; K=4 hit fma-rt (19ops x 4 x rt2).
// Fix: K=3 scalar interleave (2-instr gaps) + direct-gw step (13 fma-ops:
// gw = w^3*sqrt(w), w = rn*kx) -> predicted iterCost(3) ~95-110 for 3 steps.
// Validated accuracy scheme unchanged: W_ZERO=176, W_WARM=160, WARM_T0=416.
// ---------------------------------------------------------------------------

#define T_MAX 262144
constexpr int L       = 8;     // output steps per chain
constexpr int W_WARM  = 160;   // warmup, warm-started blocks (b >= 1)
constexpr int W_ZERO  = 176;   // warmup, block 0 (zero-start region)
constexpr int BLK     = 32;    // threads/block (1 warp), 3 chains/thread
constexpr int CPB     = BLK * 3;             // 96 chains/block
constexpr int OSZ     = CPB * L;             // 768 outputs/block
constexpr int WSZ     = W_ZERO + OSZ;        // 944 max window
constexpr int WSZP    = WSZ + WSZ / 32;      // 973
constexpr int OSZP    = OSZ + OSZ / 32;      // 792
constexpr int SPRN    = WSZ + 5;             // 949 raw pr window
constexpr int WARM_T0 = 416;   // chains with t0 >= this warm-start from r^

__device__ __forceinline__ float fsqrt_approx(float x) {
    float y; asm("sqrt.approx.f32 %0, %1;" : "=f"(y) : "f"(x)); return y;
}
__device__ __forceinline__ int padi(int d) { return d + (d >> 5); }

// Unit-hydrograph ordinates for X4 = 2.5 (o2[5] = 0 exactly):
#define O1_0 0.10119288512538814f
#define O1_1 0.47124051711455807f
#define O1_2 0.42756659776005380f
#define O2_0 0.05059644256269407f
#define O2_1 0.23562025855727903f
#define O2_2 0.42756659776005380f
#define O2_3 0.23562025855727903f
#define O2_4 0.05059644256269407f

// (1+u)^(-1/4) deg-4 Horner
#define P1 (-0.25f)
#define P2 ( 0.15625f)
#define P3 (-0.1171875f)
#define P4 ( 0.0952148438f)

// Triple-chain direct-gw step, scalar-interleaved (2-instr latency gaps).
// Updates za/gwa, zb/gwb, zc/gwc; exposes sa..sc, rna..rnc.
#define TRI_STEP(c1a, c1b, c1c)                                               \
    float sa = fmaxf(za + c1a, 0.0f);                                         \
    float sb = fmaxf(zb + c1b, 0.0f);                                         \
    float sc = fmaxf(zc + c1c, 0.0f);                                         \
    float Aa = sa * sa;  float Ab = sb * sb;  float Ac = sc * sc;             \
    float ua = (Aa * inv4) * Aa;                                              \
    float ub = (Ab * inv4) * Ab;                                              \
    float uc = (Ac * inv4) * Ac;                                              \
    float pa = fmaf(ua, P4, P3);                                              \
    float pb = fmaf(ub, P4, P3);                                              \
    float pc = fmaf(uc, P4, P3);                                              \
    pa = fmaf(ua, pa, P2);  pb = fmaf(ub, pb, P2);  pc = fmaf(uc, pc, P2);    \
    pa = fmaf(ua, pa, P1);  pb = fmaf(ub, pb, P1);  pc = fmaf(uc, pc, P1);    \
    pa = fmaf(ua, pa, 1.0f); pb = fmaf(ub, pb, 1.0f); pc = fmaf(uc, pc, 1.0f);\
    float rna = sa * pa;  float rnb = sb * pb;  float rnc = sc * pc;          \
    float wa = rna * kx;  float wb = rnb * kx;  float wc = rnc * kx;          \
    float swa = fsqrt_approx(wa);                                             \
    float swb = fsqrt_approx(wb);                                             \
    float swc = fsqrt_approx(wc);                                             \
    float w3a = (wa * wa) * wa;                                               \
    float w3b = (wb * wb) * wb;                                               \
    float w3c = (wc * wc) * wc;                                               \
    gwa = w3a * swa;  gwb = w3b * swb;  gwc = w3c * swc;                      \
    za = rna + gwa;   zb = rnb + gwb;   zc = rnc + gwc;

__global__ void __launch_bounds__(BLK, 1)
scan_kernel(const float* __restrict__ x,
            const float* __restrict__ x2p,
            const float* __restrict__ x3p,
            float* __restrict__ out, int T) {
    __shared__ float spr[SPRN];
    __shared__ float s1[WSZP];
    __shared__ float s2[OSZP];     // c2 only for the output range
    __shared__ float sq[OSZP];
    __shared__ float sr[OSZP];

    int tid = threadIdx.x;
    int b   = blockIdx.x;
    int t0b = b * OSZ;
    if (t0b >= T) return;

    const int Wb  = (b == 0) ? W_ZERO : W_WARM;
    const int wsz = Wb + OSZ;

    // ---- Fused conv staging: spr[k] = pr(t0b - Wb - 5 + k) ----
    {
        int pt0 = t0b - Wb - 5;
        for (int k = tid; k < wsz + 5; k += BLK) {
            int t = pt0 + k;
            float pr = 0.0f;
            if (t >= 0 && t < T) {
                float4 row = *reinterpret_cast<const float4*>(x + 4 * t);
                pr = row.w + (row.x - row.z);   // perc + (p_n - p_s)
            }
            spr[k] = pr;
        }
    }
    __syncthreads();

    // c1 over the whole window (accumulate local sum for the solve).
    float csum = 0.0f;
    for (int d = tid; d < wsz; d += BLK) {
        float c1 = 0.9f * (O1_0 * spr[d + 5] + O1_1 * spr[d + 4]
                         + O1_2 * spr[d + 3]);
        s1[padi(d)] = c1;
        csum += c1;
    }
    // c2 only for the output range; output offset od -> time t0b + od.
    for (int d = tid; d < OSZ; d += BLK) {
        int k = d + Wb;
        float c2 = 0.1f * (O2_0 * spr[k + 5] + O2_1 * spr[k + 4]
                         + O2_2 * spr[k + 3] + O2_3 * spr[k + 2]
                         + O2_4 * spr[k + 1]);
        s2[padi(d)] = c2;
    }
    __syncthreads();

    const float x2  = __ldg(x2p);
    const float x3  = __ldg(x3p);
    const float inv = 1.0f / x3;
    const float inv2 = inv * inv, inv4 = inv2 * inv2;
    const float kx  = __powf(x2, 0.28571428571f) * inv;  // x2^(2/7)/x3

    // ---- Per-block warm-start solve: mean c1 -> 12 fixed-point iters ----
#pragma unroll
    for (int o = 16; o > 0; o >>= 1)
        csum += __shfl_xor_sync(0xffffffffu, csum, o);
    const float m = csum / (float)wsz;
    float zI = 48.0f, gwI = 0.0f;
#pragma unroll
    for (int it = 0; it < 12; ++it) {
        float s_ = fmaxf(zI + m, 0.0f);
        float A_ = s_ * s_;
        float u_ = (A_ * inv4) * A_;
        float p_ = fmaf(u_, P4, P3); p_ = fmaf(u_, p_, P2);
        p_ = fmaf(u_, p_, P1); p_ = fmaf(u_, p_, 1.0f);
        float rn_ = s_ * p_;
        float w_  = rn_ * kx;
        float sw_ = fsqrt_approx(w_);
        gwI = ((w_ * w_) * w_) * sw_;
        zI  = rn_ + gwI;
    }

    // Chains A/B/C: t0 = t0b + 8*tid + {0, 256, 512}.
    const int da0 = tid * L;
    const int db0 = da0 + 256;
    const int dc0 = da0 + 512;
    const int t0a = t0b + da0;

    float za, gwa, zb, gwb, zc, gwc;
    if (t0a       >= WARM_T0) { za = zI; gwa = gwI; } else { za = 0.0f; gwa = 0.0f; }
    if (t0a + 256 >= WARM_T0) { zb = zI; gwb = gwI; } else { zb = 0.0f; gwb = 0.0f; }
    if (t0a + 512 >= WARM_T0) { zc = zI; gwc = gwI; } else { zc = 0.0f; gwc = 0.0f; }

    // ---- Warmup: software-pipelined c1 loads (prefetch depth 1) ----
    float n1a = s1[padi(da0)];
    float n1b = s1[padi(db0)];
    float n1c = s1[padi(dc0)];
#pragma unroll 8
    for (int i = 0; i < Wb; ++i) {
        float c1a = n1a, c1b = n1b, c1c = n1c;
        n1a = s1[padi(da0 + i + 1)];
        n1b = s1[padi(db0 + i + 1)];
        n1c = s1[padi(dc0 + i + 1)];
        TRI_STEP(c1a, c1b, c1c)
        (void)rna; (void)rnb; (void)rnc;
    }

    // ---- Output phase (8 iters) ----
#pragma unroll
    for (int j = 0; j < L; ++j) {
        float c1a = s1[padi(da0 + Wb + j)], c2a = s2[padi(da0 + j)];
        float c1b = s1[padi(db0 + Wb + j)], c2b = s2[padi(db0 + j)];
        float c1c = s1[padi(dc0 + Wb + j)], c2c = s2[padi(dc0 + j)];
        float qda = fmaxf(c2a + gwa, 0.0f);   // uses OLD gw
        float qdb = fmaxf(c2b + gwb, 0.0f);
        float qdc = fmaxf(c2c + gwc, 0.0f);
        TRI_STEP(c1a, c1b, c1c)
        sq[padi(da0 + j)] = (sa - rna) + qda;  sr[padi(da0 + j)] = rna;
        sq[padi(db0 + j)] = (sb - rnb) + qdb;  sr[padi(db0 + j)] = rnb;
        sq[padi(dc0 + j)] = (sc - rnc) + qdc;  sr[padi(dc0 + j)] = rnc;
    }
    __syncthreads();

    // ---- Coalesced epilogue ----
    float* __restrict__ qout = out;        // qsim    [0, T)
    float* __restrict__ rout = out + T;    // r_store [T, 2T)
    int lim = T - t0b; if (lim > OSZ) lim = OSZ;
    for (int d = tid; d < lim; d += BLK) {
        qout[t0b + d] = sq[padi(d)];
        rout[t0b + d] = sr[padi(d)];
    }
}

extern "C" void kernel_launch(void* const* d_in, const int* in_sizes, int n_in,
                              void* d_out, int out_size) {
    const float* x  = (const float*)d_in[0];
    const float* x2 = (const float*)d_in[1];
    const float* x3 = (const float*)d_in[2];
    int T = in_sizes[0] / 4;
    if (T > T_MAX) T = T_MAX;

    int nblocks = (T + OSZ - 1) / OSZ;     // 342 for T = 262144
    scan_kernel<<<nblocks, BLK>>>(x, x2, x3, (float*)d_out, T);
}

// round 17
// speedup vs baseline: 1.1193x; 1.1193x over previous
#include <cuda_runtime.h>
#include <math.h>

// ---------------------------------------------------------------------------
// RoutingStorage (GR4J). Single fused kernel: per-block staging (raw x ->
// pr -> FIR c1/c2 in smem), per-block warm-start solve, chunk-parallel
// warmup scan.
// R17: wall = iters x iterCost(K); adding chains/thread only lengthens the
// serial iteration (K=3 regressed). Flip to K=1 with the minimal 18-op step
// and 128-thread CTAs: warps 0-3 -> SMSPs 0-3, 342 CTAs -> 2-3 co-resident
// warps per SMSP that cover each other's dependency stalls -> iterCost
// should floor near the ~64-cyc dataflow chain instead of ~150-cyc solo
// exposure. Accuracy scheme unchanged (W_ZERO=176, W_WARM=160, WARM_T0=416,
// direct-gw body -- measured 2.83e-4 in R16).
// ---------------------------------------------------------------------------

#define T_MAX 262144
constexpr int L       = 6;     // output steps per chain (1 chain/thread)
constexpr int W_WARM  = 160;   // warmup, warm-started blocks (b >= 1)
constexpr int W_ZERO  = 176;   // warmup, block 0 (zero-start region)
constexpr int BLK     = 128;   // threads/block = 4 warps -> SMSPs 0..3
constexpr int OSZ     = BLK * L;             // 768 outputs/block
constexpr int WSZ     = W_ZERO + OSZ;        // 944 max window
constexpr int WSZP    = WSZ + WSZ / 32;      // 973
constexpr int OSZP    = OSZ + OSZ / 32;      // 792
constexpr int SPRN    = WSZ + 5;             // 949 raw pr window
constexpr int WARM_T0 = 416;   // chains with t0 >= this warm-start from r^

__device__ __forceinline__ float fsqrt_approx(float x) {
    float y; asm("sqrt.approx.f32 %0, %1;" : "=f"(y) : "f"(x)); return y;
}
__device__ __forceinline__ int padi(int d) { return d + (d >> 5); }

// Unit-hydrograph ordinates for X4 = 2.5 (o2[5] = 0 exactly):
#define O1_0 0.10119288512538814f
#define O1_1 0.47124051711455807f
#define O1_2 0.42756659776005380f
#define O2_0 0.05059644256269407f
#define O2_1 0.23562025855727903f
#define O2_2 0.42756659776005380f
#define O2_3 0.23562025855727903f
#define O2_4 0.05059644256269407f

// (1+u)^(-1/4) deg-4 Horner
#define P1 (-0.25f)
#define P2 ( 0.15625f)
#define P3 (-0.1171875f)
#define P4 ( 0.0952148438f)

// Minimal direct-gw step (15 math ops): updates z, gw; exposes s, rn.
#define ONE_STEP(c1v)                                   \
    float s  = fmaxf(z + c1v, 0.0f);                    \
    float A  = s * s;                                   \
    float u  = (A * inv4) * A;                          \
    float p  = fmaf(u, P4, P3);                         \
    p = fmaf(u, p, P2);                                 \
    p = fmaf(u, p, P1);                                 \
    p = fmaf(u, p, 1.0f);                               \
    float rn = s * p;                                   \
    float w  = rn * kx;                                 \
    float sw = fsqrt_approx(w);                         \
    float w3 = (w * w) * w;                             \
    gw = w3 * sw;                                       \
    z  = rn + gw;

__global__ void __launch_bounds__(BLK, 3)
scan_kernel(const float* __restrict__ x,
            const float* __restrict__ x2p,
            const float* __restrict__ x3p,
            float* __restrict__ out, int T) {
    __shared__ float spr[SPRN];
    __shared__ float s1[WSZP];
    __shared__ float s2[OSZP];     // c2 only for the output range
    __shared__ float sq[OSZP];
    __shared__ float sr[OSZP];
    __shared__ float wsum[4];

    int tid = threadIdx.x;
    int b   = blockIdx.x;
    int t0b = b * OSZ;
    if (t0b >= T) return;

    const int Wb  = (b == 0) ? W_ZERO : W_WARM;
    const int wsz = Wb + OSZ;

    // ---- Fused conv staging: spr[k] = pr(t0b - Wb - 5 + k) ----
    {
        int pt0 = t0b - Wb - 5;
        for (int k = tid; k < wsz + 5; k += BLK) {
            int t = pt0 + k;
            float pr = 0.0f;
            if (t >= 0 && t < T) {
                float4 row = *reinterpret_cast<const float4*>(x + 4 * t);
                pr = row.w + (row.x - row.z);   // perc + (p_n - p_s)
            }
            spr[k] = pr;
        }
    }
    __syncthreads();

    // c1 over the whole window (accumulate local sum for the solve).
    float csum = 0.0f;
    for (int d = tid; d < wsz; d += BLK) {
        float c1 = 0.9f * (O1_0 * spr[d + 5] + O1_1 * spr[d + 4]
                         + O1_2 * spr[d + 3]);
        s1[padi(d)] = c1;
        csum += c1;
    }
    // c2 only for the output range; output offset od -> time t0b + od.
    for (int d = tid; d < OSZ; d += BLK) {
        int k = d + Wb;
        float c2 = 0.1f * (O2_0 * spr[k + 5] + O2_1 * spr[k + 4]
                         + O2_2 * spr[k + 3] + O2_3 * spr[k + 2]
                         + O2_4 * spr[k + 1]);
        s2[padi(d)] = c2;
    }

    const float x2  = __ldg(x2p);
    const float x3  = __ldg(x3p);
    const float inv = 1.0f / x3;
    const float inv2 = inv * inv, inv4 = inv2 * inv2;
    const float kx  = __powf(x2, 0.28571428571f) * inv;  // x2^(2/7)/x3

    // ---- Block-wide mean of c1 -> warm-start fixed point (12 iters) ----
#pragma unroll
    for (int o = 16; o > 0; o >>= 1)
        csum += __shfl_xor_sync(0xffffffffu, csum, o);
    if ((tid & 31) == 0) wsum[tid >> 5] = csum;
    __syncthreads();
    const float m = (wsum[0] + wsum[1] + wsum[2] + wsum[3]) / (float)wsz;

    float zI = 48.0f, gwI = 0.0f;
#pragma unroll
    for (int it = 0; it < 12; ++it) {
        float s_ = fmaxf(zI + m, 0.0f);
        float A_ = s_ * s_;
        float u_ = (A_ * inv4) * A_;
        float p_ = fmaf(u_, P4, P3); p_ = fmaf(u_, p_, P2);
        p_ = fmaf(u_, p_, P1); p_ = fmaf(u_, p_, 1.0f);
        float rn_ = s_ * p_;
        float w_  = rn_ * kx;
        float sw_ = fsqrt_approx(w_);
        gwI = ((w_ * w_) * w_) * sw_;
        zI  = rn_ + gwI;
    }

    // ---- Chain tid: t0 = t0b + L*tid, window base d0 = L*tid ----
    const int d0  = tid * L;
    const int t0  = t0b + d0;

    float z, gw;
    if (t0 >= WARM_T0) { z = zI; gw = gwI; } else { z = 0.0f; gw = 0.0f; }

    // ---- Warmup: software-pipelined c1 loads (prefetch depth 1) ----
    float n1 = s1[padi(d0)];
#pragma unroll 8
    for (int i = 0; i < Wb; ++i) {
        float c1v = n1;
        n1 = s1[padi(d0 + i + 1)];        // next iter's input: LDS latency
        ONE_STEP(c1v)                     // overlaps this iter's math
        (void)rn;
    }

    // ---- Output phase (L iters) ----
#pragma unroll
    for (int j = 0; j < L; ++j) {
        float c1v = s1[padi(d0 + Wb + j)];
        float c2v = s2[padi(d0 + j)];
        float qd  = fmaxf(c2v + gw, 0.0f);   // uses OLD gw
        ONE_STEP(c1v)
        sq[padi(d0 + j)] = (s - rn) + qd;
        sr[padi(d0 + j)] = rn;
    }
    __syncthreads();

    // ---- Coalesced epilogue ----
    float* __restrict__ qout = out;        // qsim    [0, T)
    float* __restrict__ rout = out + T;    // r_store [T, 2T)
    int lim = T - t0b; if (lim > OSZ) lim = OSZ;
    for (int d = tid; d < lim; d += BLK) {
        qout[t0b + d] = sq[padi(d)];
        rout[t0b + d] = sr[padi(d)];
    }
}

extern "C" void kernel_launch(void* const* d_in, const int* in_sizes, int n_in,
                              void* d_out, int out_size) {
    const float* x  = (const float*)d_in[0];
    const float* x2 = (const float*)d_in[1];
    const float* x3 = (const float*)d_in[2];
    int T = in_sizes[0] / 4;
    if (T > T_MAX) T = T_MAX;

    int nblocks = (T + OSZ - 1) / OSZ;     // 342 for T = 262144
    scan_kernel<<<nblocks, BLK>>>(x, x2, x3, (float*)d_out, T);
}